// round 1
// baseline (speedup 1.0000x reference)
#include <cuda_runtime.h>
#include <cstdint>

// ---------------------------------------------------------------------------
// CRLI forward. B=32768, S=16, H=16, LATENT=16.
// out layout (fp32): [0,BS) imputed | [BS,2BS) disc | [2BS,3BS) latent | [3BS,4BS) recon
// where BS = B*16 (S == LATENT == 16 so all sections are equal length).
// ---------------------------------------------------------------------------

#define S16 16
#define H16 16

// scratch computed once per launch by setup_kernel (same values every replay ->
// deterministic, graph-capturable, no allocation)
__device__ float g_init[64];       // h_f0[16], c_f0[16], h_b0[16], c_b0[16]
__device__ float g_dec_recon[16];  // reconstructed[s] (batch-independent)

// ---- fast-but-accurate activations (ex2/rcp approx, ~1e-7 rel err) --------
__device__ __forceinline__ float fast_ex2(float x) {
    float y; asm("ex2.approx.f32 %0, %1;" : "=f"(y) : "f"(x)); return y;
}
__device__ __forceinline__ float fast_rcp(float x) {
    float y; asm("rcp.approx.f32 %0, %1;" : "=f"(y) : "f"(x)); return y;
}
__device__ __forceinline__ float sigmoidf_(float x) {
    // 1/(1+e^-x); saturates correctly at +-inf via ex2/rcp special cases
    return fast_rcp(1.0f + fast_ex2(-1.4426950408889634f * x));
}
__device__ __forceinline__ float tanhf_(float x) {
    // 2/(1+e^-2x) - 1
    float t = fast_ex2(-2.8853901f * x);
    return fmaf(2.0f, fast_rcp(1.0f + t), -1.0f);
}

// dot over N (multiple of 4) smem weights (16B-aligned rows) x register vector
template <int N>
__device__ __forceinline__ float dotN_acc(const float* __restrict__ w,
                                          const float* __restrict__ v, float acc) {
#pragma unroll
    for (int k = 0; k < N; k += 4) {
        float4 wv = *reinterpret_cast<const float4*>(w + k);
        acc = fmaf(v[k + 0], wv.x, acc);
        acc = fmaf(v[k + 1], wv.y, acc);
        acc = fmaf(v[k + 2], wv.z, acc);
        acc = fmaf(v[k + 3], wv.w, acc);
    }
    return acc;
}

// one LSTM cell step, H=16, scalar input cc. h,c live in registers.
__device__ __forceinline__ void lstm_step16(float h[16], float c[16], float cc,
                                            const float* __restrict__ U,     // [64][16] smem
                                            const float* __restrict__ wih,   // [64] smem
                                            const float* __restrict__ bias)  // [64] smem
{
    float hn[16];
#pragma unroll
    for (int j = 0; j < 16; j++) {
        float gi = dotN_acc<16>(U + (j +  0) * 16, h, fmaf(cc, wih[j +  0], bias[j +  0]));
        float gf = dotN_acc<16>(U + (j + 16) * 16, h, fmaf(cc, wih[j + 16], bias[j + 16]));
        float gg = dotN_acc<16>(U + (j + 32) * 16, h, fmaf(cc, wih[j + 32], bias[j + 32]));
        float go = dotN_acc<16>(U + (j + 48) * 16, h, fmaf(cc, wih[j + 48], bias[j + 48]));
        float cn = fmaf(sigmoidf_(gf), c[j], sigmoidf_(gi) * tanhf_(gg));
        c[j] = cn;
        hn[j] = sigmoidf_(go) * tanhf_(cn);
    }
#pragma unroll
    for (int j = 0; j < 16; j++) h[j] = hn[j];
}

// ---------------------------------------------------------------------------
// Kernel 1: batch-independent precompute. 1 block, 32 threads.
//   - generator fwd/bwd initial (h,c) from the x=+-128 warmup step
//   - full decoder recurrence -> g_dec_recon[16]
// ---------------------------------------------------------------------------
__global__ void setup_kernel(const float* __restrict__ gfW, const float* __restrict__ gfb,
                             const float* __restrict__ gbW, const float* __restrict__ gbb,
                             const float* __restrict__ dWih, const float* __restrict__ dWhh,
                             const float* __restrict__ db,
                             const float* __restrict__ dOW, const float* __restrict__ dOB)
{
    int tid = threadIdx.x;
    __shared__ float shd[16], scd[16];

    if (tid < 16) {
        // gen fwd init: gates = 128*Wih + b, h=c=0
        {
            float gi = fmaf(128.0f, gfW[tid +  0], gfb[tid +  0]);
            float gg = fmaf(128.0f, gfW[tid + 32], gfb[tid + 32]);
            float go = fmaf(128.0f, gfW[tid + 48], gfb[tid + 48]);
            float c = sigmoidf_(gi) * tanhf_(gg);
            float h = sigmoidf_(go) * tanhf_(c);
            g_init[tid] = h;  g_init[16 + tid] = c;
        }
        // gen bwd init: x = -128
        {
            float gi = fmaf(-128.0f, gbW[tid +  0], gbb[tid +  0]);
            float gg = fmaf(-128.0f, gbW[tid + 32], gbb[tid + 32]);
            float go = fmaf(-128.0f, gbW[tid + 48], gbb[tid + 48]);
            float c = sigmoidf_(gi) * tanhf_(gg);
            float h = sigmoidf_(go) * tanhf_(c);
            g_init[32 + tid] = h;  g_init[48 + tid] = c;
        }
        // decoder init: x = full(128, 16), h=c=0
        {
            float si = db[tid], sg = db[tid + 32], so = db[tid + 48];
            for (int k = 0; k < 16; k++) {
                si = fmaf(128.0f, dWih[(tid +  0) * 16 + k], si);
                sg = fmaf(128.0f, dWih[(tid + 32) * 16 + k], sg);
                so = fmaf(128.0f, dWih[(tid + 48) * 16 + k], so);
            }
            float c = sigmoidf_(si) * tanhf_(sg);
            float h = sigmoidf_(so) * tanhf_(c);
            shd[tid] = h; scd[tid] = c;
        }
    }
    __syncthreads();

    for (int s = 0; s < S16; s++) {
        float gi = 0.f, gf = 0.f, gg = 0.f, go = 0.f;
        if (tid < 16) {
            gi = db[tid]; gf = db[tid + 16]; gg = db[tid + 32]; go = db[tid + 48];
            for (int k = 0; k < 16; k++) {
                float xk = scd[k], hk = shd[k];   // x input = previous cell state
                gi = fmaf(xk, dWih[(tid +  0) * 16 + k], fmaf(hk, dWhh[(tid +  0) * 16 + k], gi));
                gf = fmaf(xk, dWih[(tid + 16) * 16 + k], fmaf(hk, dWhh[(tid + 16) * 16 + k], gf));
                gg = fmaf(xk, dWih[(tid + 32) * 16 + k], fmaf(hk, dWhh[(tid + 32) * 16 + k], gg));
                go = fmaf(xk, dWih[(tid + 48) * 16 + k], fmaf(hk, dWhh[(tid + 48) * 16 + k], go));
            }
        }
        __syncthreads();
        if (tid < 16) {
            float c = fmaf(sigmoidf_(gf), scd[tid], sigmoidf_(gi) * tanhf_(gg));
            float h = sigmoidf_(go) * tanhf_(c);
            scd[tid] = c; shd[tid] = h;
        }
        __syncthreads();
        if (tid == 0) {
            float acc = dOB[0];
            for (int k = 0; k < 16; k++) acc = fmaf(shd[k], dOW[k], acc);
            g_dec_recon[s] = acc;
        }
        __syncthreads();
    }
}

// ---------------------------------------------------------------------------
// Kernel 2: generator. One thread per batch row. Writes imputed + latent.
// ---------------------------------------------------------------------------
__global__ void __launch_bounds__(128)
gen_kernel(const float* __restrict__ values, const int* __restrict__ masks,
           const float* __restrict__ gfU, const float* __restrict__ gfW, const float* __restrict__ gfb,
           const float* __restrict__ gbU, const float* __restrict__ gbW, const float* __restrict__ gbb,
           const float* __restrict__ impW, const float* __restrict__ impB,
           const float* __restrict__ fcW, const float* __restrict__ fcB,
           float* __restrict__ out, int B)
{
    __shared__ __align__(16) float sUf[1024], sUb[1024];
    __shared__ __align__(16) float sWf[64], sWb[64], sBf[64], sBb[64];
    __shared__ __align__(16) float sImpW[16], sFcW[256], sFcB[16], sInit[64];

    int tid = threadIdx.x;
    for (int i = tid; i < 1024; i += 128) { sUf[i] = gfU[i]; sUb[i] = gbU[i]; }
    for (int i = tid; i < 64; i += 128) {
        sWf[i] = gfW[i]; sWb[i] = gbW[i]; sBf[i] = gfb[i]; sBb[i] = gbb[i];
        sInit[i] = g_init[i];
    }
    for (int i = tid; i < 256; i += 128) sFcW[i] = fcW[i];
    if (tid < 16) { sImpW[tid] = impW[tid]; sFcB[tid] = fcB[tid]; }
    __syncthreads();

    int b = blockIdx.x * 128 + tid;
    if (b >= B) return;
    float impb = __ldg(impB);

    const float* vrow = values + (size_t)b * S16;
    const int*   mrow = masks  + (size_t)b * S16;

    float hf[16], cf[16], hb[16], cb[16];
#pragma unroll
    for (int k = 0; k < 16; k++) {
        hf[k] = sInit[k]; cf[k] = sInit[16 + k];
        hb[k] = sInit[32 + k]; cb[k] = sInit[48 + k];
    }

#pragma unroll 1
    for (int t = 0; t < S16; t++) {
        float xt = __ldg(vrow + t);
        float mt = (float)__ldg(mrow + t);
        float df = dotN_acc<16>(sImpW, hf, impb);
        float db = dotN_acc<16>(sImpW, hb, impb);
        float ccf = fmaf(mt, df - xt, xt);   // (1-m)*x + m*imp, m in {0,1}
        float ccb = fmaf(mt, db - xt, xt);
        lstm_step16(hf, cf, ccf, sUf, sWf, sBf);
        lstm_step16(hb, cb, ccb, sUb, sWb, sBb);
    }

    float h[16];
#pragma unroll
    for (int k = 0; k < 16; k++) h[k] = hf[k] + hb[k];

    size_t BS = (size_t)B * S16;

    // imputed: h[s]*(1-m) + x*m
    float impv[16];
#pragma unroll
    for (int s = 0; s < 16; s++) {
        float xt = __ldg(vrow + s);
        float mt = (float)__ldg(mrow + s);
        impv[s] = fmaf(mt, xt - h[s], h[s]);
    }
    float4* o4 = reinterpret_cast<float4*>(out + (size_t)b * 16);
#pragma unroll
    for (int i = 0; i < 4; i++)
        o4[i] = make_float4(impv[4 * i], impv[4 * i + 1], impv[4 * i + 2], impv[4 * i + 3]);

    // latent = h @ fcW.T + fcB
    float lat[16];
#pragma unroll
    for (int l = 0; l < 16; l++) lat[l] = dotN_acc<16>(sFcW + l * 16, h, sFcB[l]);
    float4* l4 = reinterpret_cast<float4*>(out + 2 * BS + (size_t)b * 16);
#pragma unroll
    for (int i = 0; i < 4; i++)
        l4[i] = make_float4(lat[4 * i], lat[4 * i + 1], lat[4 * i + 2], lat[4 * i + 3]);
}

// ---------------------------------------------------------------------------
// Kernel 3: discriminator per (b,s) sample + recon broadcast fill.
// NOTE: the 'f' gate of each disc layer is dead in the reference -> skipped.
// ---------------------------------------------------------------------------
__global__ void __launch_bounds__(256)
disc_kernel(const float* __restrict__ W0, const float* __restrict__ b0,
            const float* __restrict__ W1, const float* __restrict__ b1,
            const float* __restrict__ W2, const float* __restrict__ b2,
            const float* __restrict__ W3, const float* __restrict__ b3,
            const float* __restrict__ W4, const float* __restrict__ b4,
            const float* __restrict__ dow, const float* __restrict__ dob,
            float* out, int BS)
{
    __shared__ __align__(16) float sW1[2048], sW4[2048], sW2[512], sW3[512];
    __shared__ __align__(16) float sW0[128], sb0[128], sb1[64], sb2[32], sb3[64], sb4[128];
    __shared__ __align__(16) float sDow[32], sRec[16];

    int tid = threadIdx.x;
    for (int i = tid; i < 2048; i += 256) { sW1[i] = W1[i]; sW4[i] = W4[i]; }
    for (int i = tid; i < 512;  i += 256) { sW2[i] = W2[i]; sW3[i] = W3[i]; }
    for (int i = tid; i < 128;  i += 256) { sW0[i] = W0[i]; sb0[i] = b0[i]; sb4[i] = b4[i]; }
    if (tid < 64) { sb1[tid] = b1[tid]; sb3[tid] = b3[tid]; }
    if (tid < 32) { sb2[tid] = b2[tid]; sDow[tid] = dow[tid]; }
    if (tid < 16) { sRec[tid] = g_dec_recon[tid]; }
    __syncthreads();

    int idx = blockIdx.x * 256 + tid;
    if (idx >= BS) return;

    float a = out[idx];  // imputed (written by gen_kernel)

    // L0: 1 -> 32
    float v0[32];
#pragma unroll
    for (int j = 0; j < 32; j++) {
        float gi = fmaf(a, sW0[j +  0], sb0[j +  0]);
        float gg = fmaf(a, sW0[j + 64], sb0[j + 64]);
        float go = fmaf(a, sW0[j + 96], sb0[j + 96]);
        float cc = sigmoidf_(gi) * tanhf_(gg);
        v0[j] = sigmoidf_(go) * tanhf_(cc);
    }
    // L1: 32 -> 16
    float v1[16];
#pragma unroll
    for (int j = 0; j < 16; j++) {
        float gi = dotN_acc<32>(sW1 + (j +  0) * 32, v0, sb1[j +  0]);
        float gg = dotN_acc<32>(sW1 + (j + 32) * 32, v0, sb1[j + 32]);
        float go = dotN_acc<32>(sW1 + (j + 48) * 32, v0, sb1[j + 48]);
        float cc = sigmoidf_(gi) * tanhf_(gg);
        v1[j] = sigmoidf_(go) * tanhf_(cc);
    }
    // L2: 16 -> 8
    float v2[8];
#pragma unroll
    for (int j = 0; j < 8; j++) {
        float gi = dotN_acc<16>(sW2 + (j +  0) * 16, v1, sb2[j +  0]);
        float gg = dotN_acc<16>(sW2 + (j + 16) * 16, v1, sb2[j + 16]);
        float go = dotN_acc<16>(sW2 + (j + 24) * 16, v1, sb2[j + 24]);
        float cc = sigmoidf_(gi) * tanhf_(gg);
        v2[j] = sigmoidf_(go) * tanhf_(cc);
    }
    // L3: 8 -> 16
    float v3[16];
#pragma unroll
    for (int j = 0; j < 16; j++) {
        float gi = dotN_acc<8>(sW3 + (j +  0) * 8, v2, sb3[j +  0]);
        float gg = dotN_acc<8>(sW3 + (j + 32) * 8, v2, sb3[j + 32]);
        float go = dotN_acc<8>(sW3 + (j + 48) * 8, v2, sb3[j + 48]);
        float cc = sigmoidf_(gi) * tanhf_(gg);
        v3[j] = sigmoidf_(go) * tanhf_(cc);
    }
    // L4: 16 -> 32
    float v4[32];
#pragma unroll
    for (int j = 0; j < 32; j++) {
        float gi = dotN_acc<16>(sW4 + (j +  0) * 16, v3, sb4[j +  0]);
        float gg = dotN_acc<16>(sW4 + (j + 64) * 16, v3, sb4[j + 64]);
        float go = dotN_acc<16>(sW4 + (j + 96) * 16, v3, sb4[j + 96]);
        float cc = sigmoidf_(gi) * tanhf_(gg);
        v4[j] = sigmoidf_(go) * tanhf_(cc);
    }
    // disc output scalar
    float r = dotN_acc<32>(sDow, v4, __ldg(dob));
    out[(size_t)BS + idx] = r;

    // reconstructed is batch-independent: broadcast fill, coalesced
    out[3 * (size_t)BS + idx] = sRec[tid & 15];
}

// ---------------------------------------------------------------------------
extern "C" void kernel_launch(void* const* d_in, const int* in_sizes, int n_in,
                              void* d_out, int out_size)
{
    const float* values = (const float*)d_in[0];
    const int*   masks  = (const int*)  d_in[1];
    const float* gfW = (const float*)d_in[2];
    const float* gfU = (const float*)d_in[3];
    const float* gfb = (const float*)d_in[4];
    const float* gbW = (const float*)d_in[5];
    const float* gbU = (const float*)d_in[6];
    const float* gbb = (const float*)d_in[7];
    const float* impW = (const float*)d_in[8];
    const float* impB = (const float*)d_in[9];
    const float* fcW  = (const float*)d_in[10];
    const float* fcB  = (const float*)d_in[11];
    const float* dWih = (const float*)d_in[12];
    const float* dWhh = (const float*)d_in[13];
    const float* db   = (const float*)d_in[14];
    const float* dOW  = (const float*)d_in[15];
    const float* dOB  = (const float*)d_in[16];
    const float* dow  = (const float*)d_in[17];
    const float* dob  = (const float*)d_in[18];
    const float* W0 = (const float*)d_in[19]; const float* b0 = (const float*)d_in[20];
    const float* W1 = (const float*)d_in[21]; const float* b1 = (const float*)d_in[22];
    const float* W2 = (const float*)d_in[23]; const float* b2 = (const float*)d_in[24];
    const float* W3 = (const float*)d_in[25]; const float* b3 = (const float*)d_in[26];
    const float* W4 = (const float*)d_in[27]; const float* b4 = (const float*)d_in[28];

    float* out = (float*)d_out;
    int B  = in_sizes[0] / 16;     // 32768
    int BS = B * 16;               // 524288

    setup_kernel<<<1, 32>>>(gfW, gfb, gbW, gbb, dWih, dWhh, db, dOW, dOB);
    gen_kernel<<<(B + 127) / 128, 128>>>(values, masks, gfU, gfW, gfb,
                                         gbU, gbW, gbb, impW, impB, fcW, fcB, out, B);
    disc_kernel<<<(BS + 255) / 256, 256>>>(W0, b0, W1, b1, W2, b2, W3, b3, W4, b4,
                                           dow, dob, out, BS);
}